// round 6
// baseline (speedup 1.0000x reference)
#include <cuda_runtime.h>
#include <cuda_bf16.h>
#include <mma.h>
#include <cstdint>
#include <cstddef>

using namespace nvcuda;

#define T_SEQ 1024
#define B_SZ  64
// E = 256, H = 256, 4H = 1024

// ---------------- device-global scratch (no allocations) ----------------
__device__ float g_x   [(size_t)B_SZ * T_SEQ * 256];   // gathered embeddings
__device__ float g_xw1f[(size_t)B_SZ * T_SEQ * 1024];  // x @ fw1_Wi
__device__ float g_xw1b[(size_t)B_SZ * T_SEQ * 1024];  // x @ bw1_Wi
__device__ float g_xw2 [(size_t)B_SZ * T_SEQ * 1024];  // x1 @ fw2_Wi
__device__ float g_x1  [(size_t)B_SZ * T_SEQ * 512];   // layer-1 output [fwd|bwd]
__device__ float g_h2f [B_SZ * 256];                   // layer-2 fwd final h

// ---------------- helpers ----------------
__device__ __forceinline__ float sigf(float x) {
    return __fdividef(1.0f, 1.0f + __expf(-x));
}
__device__ __forceinline__ float tanhfast(float x) {
    float e = __expf(2.0f * x);
    return 1.0f - __fdividef(2.0f, e + 1.0f);
}
__device__ __forceinline__ uint32_t smem_u32(const void* p) {
    uint32_t a;
    asm("{ .reg .u64 t; cvta.to.shared.u64 t, %1; cvt.u32.u64 %0, t; }" : "=r"(a) : "l"(p));
    return a;
}
__device__ __forceinline__ void mbar_init(uint32_t a, uint32_t cnt) {
    asm volatile("mbarrier.init.shared.b64 [%0], %1;" :: "r"(a), "r"(cnt) : "memory");
}
__device__ __forceinline__ void mbar_arrive_expect_tx(uint32_t a, uint32_t tx) {
    asm volatile("mbarrier.arrive.expect_tx.shared.b64 _, [%0], %1;" :: "r"(a), "r"(tx) : "memory");
}
__device__ __forceinline__ void mbar_arrive_remote(uint32_t la, uint32_t rank) {
    asm volatile(
        "{\n\t.reg .b32 ra;\n\t"
        "mapa.shared::cluster.u32 ra, %0, %1;\n\t"
        "mbarrier.arrive.shared::cluster.b64 _, [ra];\n\t}"
        :: "r"(la), "r"(rank) : "memory");
}
__device__ __forceinline__ void mbar_wait(uint32_t a, uint32_t parity) {
    asm volatile(
        "{\n\t.reg .pred P;\n"
        "W%=:\n\t"
        "mbarrier.try_wait.parity.acquire.cluster.shared::cta.b64 P, [%0], %1, 0x989680;\n\t"
        "@P bra D%=;\n\t"
        "bra W%=;\n"
        "D%=:\n\t}"
        :: "r"(a), "r"(parity) : "memory");
}
__device__ __forceinline__ void bulk_to_peer(uint32_t dst_la, uint32_t src_la,
                                             uint32_t bytes, uint32_t mbar_la, uint32_t rank) {
    asm volatile(
        "{\n\t.reg .b32 rd, rm;\n\t"
        "mapa.shared::cluster.u32 rd, %0, %3;\n\t"
        "mapa.shared::cluster.u32 rm, %2, %3;\n\t"
        "cp.async.bulk.shared::cluster.shared::cta.mbarrier::complete_tx::bytes [rd], [%1], %4, [rm];\n\t}"
        :: "r"(dst_la), "r"(src_la), "r"(mbar_la), "r"(rank), "r"(bytes) : "memory");
}

// ---------------- embedding gather ----------------
__global__ void gather_kernel(const int* __restrict__ tok, const float* __restrict__ emb) {
    size_t idx = (size_t)blockIdx.x * blockDim.x + threadIdx.x;  // 65536*64 float4
    int row = (int)(idx >> 6);
    int f   = (int)(idx & 63);
    int t   = __ldg(&tok[row]);
    ((float4*)g_x)[idx] = __ldg(&((const float4*)emb)[(size_t)t * 64 + f]);
}

// ---------------- bf16 WMMA GEMM: C[M,N] = A[M,K] @ B[K,N] ----------------
#define GLDA 40
#define GLDB 136
__global__ __launch_bounds__(256) void gemm_bf16(const float* __restrict__ A,
                                                 const float* __restrict__ B,
                                                 float* __restrict__ C,
                                                 int N, int K) {
    __shared__ __nv_bfloat16 As[128 * GLDA];
    __shared__ __nv_bfloat16 Bs[32 * GLDB];
    const int tid = threadIdx.x;
    const int w   = tid >> 5;
    const int m0  = blockIdx.y * 128;
    const int n0  = blockIdx.x * 128;
    const int wm0 = (w >> 2) * 64;
    const int wn0 = (w & 3) * 32;

    wmma::fragment<wmma::accumulator, 16, 16, 16, float> c[4][2];
    #pragma unroll
    for (int i = 0; i < 4; i++)
        #pragma unroll
        for (int j = 0; j < 2; j++) wmma::fill_fragment(c[i][j], 0.0f);

    const int nkt = K >> 5;
    for (int kt = 0; kt < nkt; kt++) {
        #pragma unroll
        for (int p = 0; p < 4; p++) {
            int idx = tid + p * 256;
            int row = idx >> 3, c4 = idx & 7;
            float4 v = __ldg(&((const float4*)(A + (size_t)(m0 + row) * K + kt * 32))[c4]);
            __nv_bfloat162* dst = (__nv_bfloat162*)(As + row * GLDA + c4 * 4);
            dst[0] = __floats2bfloat162_rn(v.x, v.y);
            dst[1] = __floats2bfloat162_rn(v.z, v.w);
        }
        #pragma unroll
        for (int p = 0; p < 4; p++) {
            int idx = tid + p * 256;
            int row = idx >> 5, c4 = idx & 31;
            float4 v = __ldg(&((const float4*)(B + (size_t)(kt * 32 + row) * N + n0))[c4]);
            __nv_bfloat162* dst = (__nv_bfloat162*)(Bs + row * GLDB + c4 * 4);
            dst[0] = __floats2bfloat162_rn(v.x, v.y);
            dst[1] = __floats2bfloat162_rn(v.z, v.w);
        }
        __syncthreads();
        #pragma unroll
        for (int kk = 0; kk < 32; kk += 16) {
            wmma::fragment<wmma::matrix_a, 16, 16, 16, __nv_bfloat16, wmma::row_major> a[4];
            wmma::fragment<wmma::matrix_b, 16, 16, 16, __nv_bfloat16, wmma::row_major> b[2];
            #pragma unroll
            for (int i = 0; i < 4; i++)
                wmma::load_matrix_sync(a[i], &As[(wm0 + i * 16) * GLDA + kk], GLDA);
            #pragma unroll
            for (int j = 0; j < 2; j++)
                wmma::load_matrix_sync(b[j], &Bs[kk * GLDB + wn0 + j * 16], GLDB);
            #pragma unroll
            for (int i = 0; i < 4; i++)
                #pragma unroll
                for (int j = 0; j < 2; j++)
                    wmma::mma_sync(c[i][j], a[i], b[j], c[i][j]);
        }
        __syncthreads();
    }
    #pragma unroll
    for (int i = 0; i < 4; i++)
        #pragma unroll
        for (int j = 0; j < 2; j++)
            wmma::store_matrix_sync(C + (size_t)(m0 + wm0 + i * 16) * N + n0 + wn0 + j * 16,
                                    c[i][j], N, wmma::mem_row_major);
}

// ---------------- persistent LSTM scan: cluster-8, mbarrier dataflow pipeline ----------------
// Cluster of 8 CTAs = one (dir, batch-group of 8 rows). CTA rank owns 32 h-cols
// (=> 128 local z-cols, c = gate*32 + j). Wh slice (256x128) bf16 in SMEM.
// h ring: 4 buffers, each [8 ranks][16 rows][32 cols] bf16 (rows 8..15 zero).
// Producers push 512B blocks via cp.async.bulk.shared::cluster with complete_tx on
// the peer's full[buf]; consumers try_wait. empty[buf] (count 8) gives backpressure.
#define WHS_LD 136
#define NBUF 4
#define BUF_BYTES 8192                                  // 8 ranks * 16*32 bf16
#define BLK_BYTES 1024
#define WHS_BYTES (256 * WHS_LD * 2)                    // 69632
#define HS_OFF    WHS_BYTES                             // 69632
#define ZB_OFF    (HS_OFF + NBUF * BUF_BYTES)           // 102400
#define ZB_LD     132
#define ZB_BYTES  (16 * ZB_LD * 4)                      // 8448
#define STG_OFF   (ZB_OFF + ZB_BYTES)                   // 110848
#define STG_BYTES 1024                                  // 2 parity buffers x 512B
#define MBAR_OFF  (STG_OFF + STG_BYTES)                 // 111872
#define SCAN_SMEM (MBAR_OFF + 64)                       // 111936

__global__ __launch_bounds__(256, 1) void scan_kernel(
    const float* __restrict__ xw_f, const float* __restrict__ xw_b,
    const float* __restrict__ Wh_f, const float* __restrict__ Wh_b,
    const float* __restrict__ b_f,  const float* __restrict__ b_b,
    float* x1out, float* h2out) {
    extern __shared__ char sm[];
    __nv_bfloat16* Whs = (__nv_bfloat16*)sm;
    __nv_bfloat16* hs  = (__nv_bfloat16*)(sm + HS_OFF);
    float*         zb  = (float*)(sm + ZB_OFF);
    __nv_bfloat16* stg = (__nv_bfloat16*)(sm + STG_OFF);

    const int tid = threadIdx.x;
    const int w   = tid >> 5;
    const int dir = blockIdx.x >> 6;                  // scan2: always 0
    const int grp = (blockIdx.x >> 3) & 7;
    uint32_t rank;
    asm("mov.u32 %0, %%cluster_ctarank;" : "=r"(rank));
    const int r0  = grp * 8;
    const int hc0 = (int)rank * 32;

    const float* xw   = dir ? xw_b : xw_f;
    const float* Whg  = dir ? Wh_b : Wh_f;
    const float* bias = dir ? b_b  : b_f;

    const uint32_t base32 = smem_u32(sm);
    const uint32_t full_mb  = base32 + MBAR_OFF;        // full[b] = +8b
    const uint32_t empty_mb = base32 + MBAR_OFF + 32;   // empty[b] = +8b

    // zero all h buffers (rows 8..15 stay zero forever)
    for (int i = tid; i < NBUF * BUF_BYTES / 4; i += 256) ((uint32_t*)hs)[i] = 0u;
    // stage Wh slice bf16: Whs[k][c], c = gate*32+j -> global col gate*256+hc0+j
    for (int i = tid; i < 256 * 128; i += 256) {
        int k = i >> 7, cc = i & 127;
        int gt = cc >> 5, j = cc & 31;
        Whs[k * WHS_LD + cc] =
            __float2bfloat16_rn(__ldg(&Whg[(size_t)k * 1024 + gt * 256 + hc0 + j]));
    }
    // gate role: row r (0..7), col j (0..31) -> global h index (r0+r, hc0+j)
    const int r = tid >> 5, j = tid & 31;
    const int colbase = hc0 + j;
    const float bi  = __ldg(&bias[0 * 256 + colbase]);
    const float bfv = __ldg(&bias[1 * 256 + colbase]);
    const float bgv = __ldg(&bias[2 * 256 + colbase]);
    const float bo  = __ldg(&bias[3 * 256 + colbase]);
    float c_state = 0.0f;
    __syncthreads();

    // init mbarriers + arm full[0..3] (each phase: 1 arrive + 4096B tx)
    if (tid == 0) {
        #pragma unroll
        for (int b = 0; b < NBUF; b++) {
            mbar_init(full_mb + 8 * b, 1);
            mbar_init(empty_mb + 8 * b, 8);
            mbar_arrive_expect_tx(full_mb + 8 * b, 8 * 512);
        }
    }
    __syncthreads();
    asm volatile("barrier.cluster.arrive.aligned;" ::: "memory");
    asm volatile("barrier.cluster.wait.aligned;"   ::: "memory");
    // pre-complete phase 0 of every empty barrier (8 arrives each)
    if (tid == 0) {
        #pragma unroll
        for (int b = 0; b < NBUF; b++)
            #pragma unroll
            for (int p = 0; p < 8; p++)
                mbar_arrive_remote(empty_mb + 8 * b, p);
    }

    // prefetch xw for step 0
    float xwi, xwf, xwg, xwo;
    {
        int t0 = dir ? (T_SEQ - 1) : 0;
        const float* p = xw + ((size_t)(r0 + r) * T_SEQ + t0) * 1024 + colbase;
        xwi = __ldcs(p); xwf = __ldcs(p + 256); xwg = __ldcs(p + 512); xwo = __ldcs(p + 768);
    }

    for (int s = 0; s < T_SEQ; s++) {
        const int t_in = dir ? (T_SEQ - 1 - s) : s;
        const int buf = s & 3;

        if (s > 0) {
            // wait h buffer (parity ((s-1)>>2)&1), then MMA: z = h @ Whs
            mbar_wait(full_mb + 8 * buf, ((unsigned)(s - 1) >> 2) & 1);
            const int n0 = w * 16;
            const __nv_bfloat16* hcur = hs + buf * (BUF_BYTES / 2);
            wmma::fragment<wmma::accumulator, 16, 16, 16, float> acc0, acc1;
            wmma::fill_fragment(acc0, 0.0f);
            wmma::fill_fragment(acc1, 0.0f);
            #pragma unroll
            for (int rk = 0; rk < 8; rk++) {
                wmma::fragment<wmma::matrix_a, 16, 16, 16, __nv_bfloat16, wmma::row_major> a0, a1;
                wmma::fragment<wmma::matrix_b, 16, 16, 16, __nv_bfloat16, wmma::row_major> b0, b1;
                const __nv_bfloat16* blk = hcur + rk * 512;
                const int kg = rk * 32;
                wmma::load_matrix_sync(a0, blk, 32);
                wmma::load_matrix_sync(b0, Whs + kg * WHS_LD + n0, WHS_LD);
                wmma::mma_sync(acc0, a0, b0, acc0);
                wmma::load_matrix_sync(a1, blk + 16, 32);
                wmma::load_matrix_sync(b1, Whs + (kg + 16) * WHS_LD + n0, WHS_LD);
                wmma::mma_sync(acc1, a1, b1, acc1);
            }
            #pragma unroll
            for (int e = 0; e < acc0.num_elements; e++) acc0.x[e] += acc1.x[e];
            wmma::store_matrix_sync(zb + n0, acc0, ZB_LD, wmma::mem_row_major);
        }
        __syncthreads();

        // gates (all 256 threads, one (row,col) each)
        {
            float zi = bi + xwi, zf = bfv + xwf, zg = bgv + xwg, zo = bo + xwo;
            if (s > 0) {
                zi += zb[r * ZB_LD +      j];
                zf += zb[r * ZB_LD + 32 + j];
                zg += zb[r * ZB_LD + 64 + j];
                zo += zb[r * ZB_LD + 96 + j];
            }
            c_state = sigf(zf) * c_state + sigf(zi) * tanhfast(zg);
            float hval = sigf(zo) * tanhfast(c_state);

            if (x1out)
                __stcg(x1out + ((size_t)(r0 + r) * T_SEQ + t_in) * 512 + dir * 256 + colbase, hval);
            if (h2out && s == T_SEQ - 1)
                h2out[(r0 + r) * 256 + colbase] = hval;

            if (s < T_SEQ - 1) {
                stg[(s & 1) * 256 + r * 32 + j] = __float2bfloat16_rn(hval);
                // prefetch xw for next step
                int tn = dir ? (T_SEQ - 2 - s) : (s + 1);
                const float* p = xw + ((size_t)(r0 + r) * T_SEQ + tn) * 1024 + colbase;
                xwi = __ldcs(p); xwf = __ldcs(p + 256); xwg = __ldcs(p + 512); xwo = __ldcs(p + 768);
            }
        }
        // consumer bookkeeping: re-arm own full[buf] (for s+4), release buf to producers
        if (s > 0 && tid == 0) {
            mbar_arrive_expect_tx(full_mb + 8 * buf, 8 * 512);
            #pragma unroll
            for (int p = 0; p < 8; p++)
                mbar_arrive_remote(empty_mb + 8 * buf, p);
        }
        __syncthreads();   // staging ready; bookkeeping ordered before producer sends

        if (s < T_SEQ - 1 && tid < 8) {
            const int wb = (s + 1) & 3;
            // wait until all 8 peers released wb (parity (s>>2)&1)
            mbar_wait(empty_mb + 8 * wb, ((unsigned)s >> 2) & 1);
            asm volatile("fence.proxy.async.shared::cta;" ::: "memory");
            const uint32_t src = base32 + STG_OFF + (s & 1) * 512;
            const uint32_t dst = base32 + HS_OFF + wb * BUF_BYTES + rank * BLK_BYTES;
            bulk_to_peer(dst, src, 512, full_mb + 8 * wb, (uint32_t)tid);
        }
    }

    // drain in-flight remote arrivals before any CTA exits
    asm volatile("barrier.cluster.arrive.aligned;" ::: "memory");
    asm volatile("barrier.cluster.wait.aligned;"   ::: "memory");
}

// ---------------- head: layer-2 bwd single step + final dot + sigmoid ----------------
__global__ __launch_bounds__(256) void head_kernel(const float* __restrict__ Wi,
                                                   const float* __restrict__ b2,
                                                   const float* __restrict__ Wd,
                                                   const float* __restrict__ bd,
                                                   float* __restrict__ out) {
    __shared__ float xr[512];
    __shared__ float z[1024];
    __shared__ float red[8];
    const int b = blockIdx.x, tid = threadIdx.x;
    const float* xrow = g_x1 + ((size_t)b * T_SEQ + (T_SEQ - 1)) * 512;
    xr[tid] = xrow[tid];
    xr[tid + 256] = xrow[tid + 256];
    __syncthreads();
    const int c0 = tid * 4;
    float4 acc = *(const float4*)(b2 + c0);
    for (int k = 0; k < 512; k++) {
        float xv = xr[k];
        float4 wv = __ldg((const float4*)(Wi + (size_t)k * 1024 + c0));
        acc.x = fmaf(xv, wv.x, acc.x);
        acc.y = fmaf(xv, wv.y, acc.y);
        acc.z = fmaf(xv, wv.z, acc.z);
        acc.w = fmaf(xv, wv.w, acc.w);
    }
    *(float4*)(z + c0) = acc;
    __syncthreads();
    float zi = z[tid], zg = z[512 + tid], zo = z[768 + tid];
    float cst = sigf(zi) * tanhf(zg);           // c0 = 0 so forget term vanishes
    float h2b = sigf(zo) * tanhf(cst);
    float pl = g_h2f[b * 256 + tid] * __ldg(&Wd[tid]) + h2b * __ldg(&Wd[256 + tid]);
    #pragma unroll
    for (int off = 16; off; off >>= 1) pl += __shfl_down_sync(0xffffffffu, pl, off);
    if ((tid & 31) == 0) red[tid >> 5] = pl;
    __syncthreads();
    if (tid == 0) {
        float ssum = 0.f;
        #pragma unroll
        for (int q = 0; q < 8; q++) ssum += red[q];
        out[b] = sigf(ssum + bd[0]);
    }
}

// ---------------- launch ----------------
static void launch_scan(int nblocks,
                        const float* xw_f, const float* xw_b,
                        const float* Wh_f, const float* Wh_b,
                        const float* b_f,  const float* b_b,
                        float* x1out, float* h2out) {
    cudaLaunchConfig_t cfg = {};
    cfg.gridDim  = dim3((unsigned)nblocks, 1, 1);
    cfg.blockDim = dim3(256, 1, 1);
    cfg.dynamicSmemBytes = SCAN_SMEM;
    cfg.stream = 0;
    cudaLaunchAttribute at[1];
    at[0].id = cudaLaunchAttributeClusterDimension;
    at[0].val.clusterDim.x = 8; at[0].val.clusterDim.y = 1; at[0].val.clusterDim.z = 1;
    cfg.attrs = at; cfg.numAttrs = 1;
    cudaLaunchKernelEx(&cfg, scan_kernel, xw_f, xw_b, Wh_f, Wh_b, b_f, b_b, x1out, h2out);
}

extern "C" void kernel_launch(void* const* d_in, const int* in_sizes, int n_in,
                              void* d_out, int out_size) {
    const int*   tokens = (const int*)  d_in[0];
    const float* embed  = (const float*)d_in[1];
    const float* fw1_Wi = (const float*)d_in[2];
    const float* fw1_Wh = (const float*)d_in[3];
    const float* fw1_b  = (const float*)d_in[4];
    const float* bw1_Wi = (const float*)d_in[5];
    const float* bw1_Wh = (const float*)d_in[6];
    const float* bw1_b  = (const float*)d_in[7];
    const float* fw2_Wi = (const float*)d_in[8];
    const float* fw2_Wh = (const float*)d_in[9];
    const float* fw2_b  = (const float*)d_in[10];
    const float* bw2_Wi = (const float*)d_in[11];
    const float* bw2_b  = (const float*)d_in[13];
    const float* Wd     = (const float*)d_in[14];
    const float* bd     = (const float*)d_in[15];
    float* out = (float*)d_out;

    float *px, *pxw1f, *pxw1b, *pxw2, *px1, *ph2f;
    cudaGetSymbolAddress((void**)&px,    g_x);
    cudaGetSymbolAddress((void**)&pxw1f, g_xw1f);
    cudaGetSymbolAddress((void**)&pxw1b, g_xw1b);
    cudaGetSymbolAddress((void**)&pxw2,  g_xw2);
    cudaGetSymbolAddress((void**)&px1,   g_x1);
    cudaGetSymbolAddress((void**)&ph2f,  g_h2f);

    cudaFuncSetAttribute(scan_kernel, cudaFuncAttributeMaxDynamicSharedMemorySize, SCAN_SMEM);

    gather_kernel<<<16384, 256>>>(tokens, embed);
    gemm_bf16<<<dim3(8, 512), 256>>>(px, fw1_Wi, pxw1f, 1024, 256);
    gemm_bf16<<<dim3(8, 512), 256>>>(px, bw1_Wi, pxw1b, 1024, 256);
    launch_scan(128, pxw1f, pxw1b, fw1_Wh, bw1_Wh, fw1_b, bw1_b, px1, nullptr);
    gemm_bf16<<<dim3(8, 512), 256>>>(px1, fw2_Wi, pxw2, 1024, 512);
    launch_scan(64, pxw2, pxw2, fw2_Wh, fw2_Wh, fw2_b, fw2_b, nullptr, ph2f);
    head_kernel<<<64, 256>>>(bw2_Wi, bw2_b, Wd, bd, out);
}

// round 8
// speedup vs baseline: 1.0765x; 1.0765x over previous
#include <cuda_runtime.h>
#include <cuda_bf16.h>
#include <mma.h>
#include <cstdint>
#include <cstddef>

using namespace nvcuda;

#define T_SEQ 1024
#define B_SZ  64
// E = 256, H = 256, 4H = 1024

// ---------------- device-global scratch (no allocations) ----------------
__device__ float g_x   [(size_t)B_SZ * T_SEQ * 256];   // gathered embeddings
__device__ float g_xw1f[(size_t)B_SZ * T_SEQ * 1024];  // x @ fw1_Wi
__device__ float g_xw1b[(size_t)B_SZ * T_SEQ * 1024];  // x @ bw1_Wi
__device__ float g_xw2 [(size_t)B_SZ * T_SEQ * 1024];  // x1 @ fw2_Wi
__device__ float g_x1  [(size_t)B_SZ * T_SEQ * 512];   // layer-1 output [fwd|bwd]
__device__ float g_h2f [B_SZ * 256];                   // layer-2 fwd final h
__device__ __nv_bfloat16 g_hb[3][2][B_SZ * 256];       // h double buffers (sets: l1f, l1b, l2)
__device__ unsigned g_ctrs[32];                        // group barrier counters

// ---------------- helpers ----------------
__device__ __forceinline__ float sigf(float x) {
    return __fdividef(1.0f, 1.0f + __expf(-x));
}
__device__ __forceinline__ float tanhfast(float x) {
    float e = __expf(2.0f * x);
    return 1.0f - __fdividef(2.0f, e + 1.0f);
}

// ---------------- init: zero barrier counters (every replay) ----------------
__global__ void init_kernel() {
    int i = threadIdx.x;
    if (i < 32) g_ctrs[i] = 0u;
}

// ---------------- embedding gather ----------------
__global__ void gather_kernel(const int* __restrict__ tok, const float* __restrict__ emb) {
    size_t idx = (size_t)blockIdx.x * blockDim.x + threadIdx.x;  // 65536*64 float4
    int row = (int)(idx >> 6);
    int f   = (int)(idx & 63);
    int t   = __ldg(&tok[row]);
    ((float4*)g_x)[idx] = __ldg(&((const float4*)emb)[(size_t)t * 64 + f]);
}

// ---------------- bf16 WMMA GEMM: C[M,N] = A[M,K] @ B[K,N] ----------------
#define GLDA 40
#define GLDB 136
__global__ __launch_bounds__(256) void gemm_bf16(const float* __restrict__ A,
                                                 const float* __restrict__ B,
                                                 float* __restrict__ C,
                                                 int N, int K) {
    __shared__ __nv_bfloat16 As[128 * GLDA];
    __shared__ __nv_bfloat16 Bs[32 * GLDB];
    const int tid = threadIdx.x;
    const int w   = tid >> 5;
    const int m0  = blockIdx.y * 128;
    const int n0  = blockIdx.x * 128;
    const int wm0 = (w >> 2) * 64;
    const int wn0 = (w & 3) * 32;

    wmma::fragment<wmma::accumulator, 16, 16, 16, float> c[4][2];
    #pragma unroll
    for (int i = 0; i < 4; i++)
        #pragma unroll
        for (int j = 0; j < 2; j++) wmma::fill_fragment(c[i][j], 0.0f);

    const int nkt = K >> 5;
    for (int kt = 0; kt < nkt; kt++) {
        #pragma unroll
        for (int p = 0; p < 4; p++) {
            int idx = tid + p * 256;
            int row = idx >> 3, c4 = idx & 7;
            float4 v = __ldg(&((const float4*)(A + (size_t)(m0 + row) * K + kt * 32))[c4]);
            __nv_bfloat162* dst = (__nv_bfloat162*)(As + row * GLDA + c4 * 4);
            dst[0] = __floats2bfloat162_rn(v.x, v.y);
            dst[1] = __floats2bfloat162_rn(v.z, v.w);
        }
        #pragma unroll
        for (int p = 0; p < 4; p++) {
            int idx = tid + p * 256;
            int row = idx >> 5, c4 = idx & 31;
            float4 v = __ldg(&((const float4*)(B + (size_t)(kt * 32 + row) * N + n0))[c4]);
            __nv_bfloat162* dst = (__nv_bfloat162*)(Bs + row * GLDB + c4 * 4);
            dst[0] = __floats2bfloat162_rn(v.x, v.y);
            dst[1] = __floats2bfloat162_rn(v.z, v.w);
        }
        __syncthreads();
        #pragma unroll
        for (int kk = 0; kk < 32; kk += 16) {
            wmma::fragment<wmma::matrix_a, 16, 16, 16, __nv_bfloat16, wmma::row_major> a[4];
            wmma::fragment<wmma::matrix_b, 16, 16, 16, __nv_bfloat16, wmma::row_major> b[2];
            #pragma unroll
            for (int i = 0; i < 4; i++)
                wmma::load_matrix_sync(a[i], &As[(wm0 + i * 16) * GLDA + kk], GLDA);
            #pragma unroll
            for (int j = 0; j < 2; j++)
                wmma::load_matrix_sync(b[j], &Bs[kk * GLDB + wn0 + j * 16], GLDB);
            #pragma unroll
            for (int i = 0; i < 4; i++)
                #pragma unroll
                for (int j = 0; j < 2; j++)
                    wmma::mma_sync(c[i][j], a[i], b[j], c[i][j]);
        }
        __syncthreads();
    }
    #pragma unroll
    for (int i = 0; i < 4; i++)
        #pragma unroll
        for (int j = 0; j < 2; j++)
            wmma::store_matrix_sync(C + (size_t)(m0 + wm0 + i * 16) * N + n0 + wn0 + j * 16,
                                    c[i][j], N, wmma::mem_row_major);
}

// ---------------- persistent LSTM scan: 4-CTA groups, L2 h exchange ----------------
// Group = (dir, batch-group of 8 rows) -> 4 CTAs. CTA owns 64 h-cols (=> 256 local
// z-cols, cc = gate*64 + c). Wh slice 256x256 bf16 in SMEM (132KB, occ 1).
// h exchanged via global bf16 double buffer + per-group release/acquire counter.
#define WHS_LD 264
#define HS_LD  264
#define ZB_LD  264
#define WHS_BYTES (256 * WHS_LD * 2)                  // 135168
#define HS_OFF    WHS_BYTES
#define HS_BYTES  (16 * HS_LD * 2)                    // 8448
#define ZB_OFF    (HS_OFF + HS_BYTES)                 // 143616
#define ZB_BYTES  (16 * ZB_LD * 4)                    // 16896
#define SCAN_SMEM (ZB_OFF + ZB_BYTES)                 // 160512

__global__ __launch_bounds__(256, 1) void scan_kernel(
    const float* __restrict__ xw_f, const float* __restrict__ xw_b,
    const float* __restrict__ Wh_f, const float* __restrict__ Wh_b,
    const float* __restrict__ b_f,  const float* __restrict__ b_b,
    __nv_bfloat16* hb_base, unsigned* ctrs,
    float* x1out, float* h2out) {
    extern __shared__ char sm[];
    __nv_bfloat16* Whs = (__nv_bfloat16*)sm;
    __nv_bfloat16* hs  = (__nv_bfloat16*)(sm + HS_OFF);
    float*         zb  = (float*)(sm + ZB_OFF);

    const int tid  = threadIdx.x;
    const int w    = tid >> 5;
    const int dir  = blockIdx.x >> 5;                 // scan2 grid=32 -> always 0
    const int grp  = (blockIdx.x >> 2) & 7;
    const int rank = blockIdx.x & 3;
    const int r0   = grp * 8;
    const int hc0  = rank * 64;

    const float* xw   = dir ? xw_b : xw_f;
    const float* Whg  = dir ? Wh_b : Wh_f;
    const float* bias = dir ? b_b  : b_f;
    __nv_bfloat16* hb = hb_base + (size_t)dir * 2 * (B_SZ * 256);
    unsigned* ctr = ctrs + dir * 8 + grp;

    // zero hs rows 8..15 once (M padded to 16; loads only rewrite rows 0..7)
    for (int i = tid; i < 16 * HS_LD; i += 256) hs[i] = __float2bfloat16(0.f);
    // stage Wh slice bf16: Whs[k][cc], cc = gate*64 + c -> global col gate*256 + hc0 + c
    for (int i = tid; i < 256 * 256; i += 256) {
        int k = i >> 8, cc = i & 255;
        int gt = cc >> 6, c = cc & 63;
        Whs[k * WHS_LD + cc] =
            __float2bfloat16_rn(__ldg(&Whg[(size_t)k * 1024 + gt * 256 + hc0 + c]));
    }

    // h-load role: row lrow (0..7), 8 bf16 (16B) per thread
    const int lrow = tid >> 5;
    const int lcol = (tid & 31) * 8;
    // gate role (tid < 128): row r (0..7), cols c0..c0+3 of this CTA's 64 h-cols
    const int r  = tid >> 4;
    const int c0 = (tid & 15) * 4;
    const int cb = hc0 + c0;
    float4 bi4 = {}, bf4 = {}, bg4 = {}, bo4 = {};
    if (tid < 128) {
        bi4 = *(const float4*)(bias + 0 * 256 + cb);
        bf4 = *(const float4*)(bias + 1 * 256 + cb);
        bg4 = *(const float4*)(bias + 2 * 256 + cb);
        bo4 = *(const float4*)(bias + 3 * 256 + cb);
    }
    float cs0 = 0.f, cs1 = 0.f, cs2 = 0.f, cs3 = 0.f;
    __syncthreads();

    // prefetch xw for step 0
    float4 xi4 = {}, xf4 = {}, xg4 = {}, xo4 = {};
    if (tid < 128) {
        int t0 = dir ? (T_SEQ - 1) : 0;
        const float* p = xw + ((size_t)(r0 + r) * T_SEQ + t0) * 1024 + cb;
        xi4 = __ldcs((const float4*)(p));
        xf4 = __ldcs((const float4*)(p + 256));
        xg4 = __ldcs((const float4*)(p + 512));
        xo4 = __ldcs((const float4*)(p + 768));
    }

    for (int s = 0; s < T_SEQ; s++) {
        const int t_in = dir ? (T_SEQ - 1 - s) : s;

        if (s > 0) {
            // wait for all 4 group CTAs to have published h(s)
            if (tid == 0) {
                const unsigned tgt = 4u * (unsigned)s;
                unsigned v;
                do {
                    asm volatile("ld.acquire.gpu.global.u32 %0, [%1];" : "=r"(v) : "l"(ctr) : "memory");
                } while (v < tgt);
            }
            __syncthreads();
            // load h(s) [8 rows x 256] bf16 from L2 into hs rows 0..7
            {
                const __nv_bfloat16* hread = hb + (s & 1) * (B_SZ * 256) + (r0 + lrow) * 256 + lcol;
                uint4 hv = __ldcg((const uint4*)hread);
                *(uint4*)(hs + lrow * HS_LD + lcol) = hv;
            }
            __syncthreads();
            // MMA: z[16,256] = h[16,256] @ Whs[256,256]; warp w -> cols [32w, 32w+32)
            const int n0 = w * 32;
            wmma::fragment<wmma::accumulator, 16, 16, 16, float> acc0, acc1;
            wmma::fill_fragment(acc0, 0.0f);
            wmma::fill_fragment(acc1, 0.0f);
            #pragma unroll
            for (int kt = 0; kt < 16; kt++) {
                wmma::fragment<wmma::matrix_a, 16, 16, 16, __nv_bfloat16, wmma::row_major> a;
                wmma::fragment<wmma::matrix_b, 16, 16, 16, __nv_bfloat16, wmma::row_major> b0, b1;
                wmma::load_matrix_sync(a, hs + kt * 16, HS_LD);
                wmma::load_matrix_sync(b0, Whs + (kt * 16) * WHS_LD + n0, WHS_LD);
                wmma::load_matrix_sync(b1, Whs + (kt * 16) * WHS_LD + n0 + 16, WHS_LD);
                wmma::mma_sync(acc0, a, b0, acc0);
                wmma::mma_sync(acc1, a, b1, acc1);
            }
            wmma::store_matrix_sync(zb + n0, acc0, ZB_LD, wmma::mem_row_major);
            wmma::store_matrix_sync(zb + n0 + 16, acc1, ZB_LD, wmma::mem_row_major);
        }
        __syncthreads();

        if (tid < 128) {
            float zi0 = bi4.x + xi4.x, zi1 = bi4.y + xi4.y, zi2 = bi4.z + xi4.z, zi3 = bi4.w + xi4.w;
            float zf0 = bf4.x + xf4.x, zf1 = bf4.y + xf4.y, zf2 = bf4.z + xf4.z, zf3 = bf4.w + xf4.w;
            float zg0 = bg4.x + xg4.x, zg1 = bg4.y + xg4.y, zg2 = bg4.z + xg4.z, zg3 = bg4.w + xg4.w;
            float zo0 = bo4.x + xo4.x, zo1 = bo4.y + xo4.y, zo2 = bo4.z + xo4.z, zo3 = bo4.w + xo4.w;
            if (s > 0) {
                const float* zr = zb + r * ZB_LD;
                zi0 += zr[c0];       zi1 += zr[c0 + 1];       zi2 += zr[c0 + 2];       zi3 += zr[c0 + 3];
                zf0 += zr[64 + c0];  zf1 += zr[64 + c0 + 1];  zf2 += zr[64 + c0 + 2];  zf3 += zr[64 + c0 + 3];
                zg0 += zr[128 + c0]; zg1 += zr[128 + c0 + 1]; zg2 += zr[128 + c0 + 2]; zg3 += zr[128 + c0 + 3];
                zo0 += zr[192 + c0]; zo1 += zr[192 + c0 + 1]; zo2 += zr[192 + c0 + 2]; zo3 += zr[192 + c0 + 3];
            }
            cs0 = sigf(zf0) * cs0 + sigf(zi0) * tanhfast(zg0);
            cs1 = sigf(zf1) * cs1 + sigf(zi1) * tanhfast(zg1);
            cs2 = sigf(zf2) * cs2 + sigf(zi2) * tanhfast(zg2);
            cs3 = sigf(zf3) * cs3 + sigf(zi3) * tanhfast(zg3);
            float h0 = sigf(zo0) * tanhfast(cs0);
            float h1 = sigf(zo1) * tanhfast(cs1);
            float h2 = sigf(zo2) * tanhfast(cs2);
            float h3 = sigf(zo3) * tanhfast(cs3);

            if (x1out) {
                float4 hv = make_float4(h0, h1, h2, h3);
                __stcg((float4*)(x1out + ((size_t)(r0 + r) * T_SEQ + t_in) * 512 + dir * 256 + cb), hv);
            }
            if (h2out && s == T_SEQ - 1)
                *(float4*)(h2out + (r0 + r) * 256 + cb) = make_float4(h0, h1, h2, h3);

            if (s < T_SEQ - 1) {
                // publish h(s+1) as 8B packed bf16x4 to global double buffer
                __nv_bfloat162 p01 = __floats2bfloat162_rn(h0, h1);
                __nv_bfloat162 p23 = __floats2bfloat162_rn(h2, h3);
                unsigned int u01 = *reinterpret_cast<unsigned int*>(&p01);
                unsigned int u23 = *reinterpret_cast<unsigned int*>(&p23);
                unsigned long long val = (unsigned long long)u01 | ((unsigned long long)u23 << 32);
                __stcg((unsigned long long*)(hb + ((s + 1) & 1) * (B_SZ * 256) + (r0 + r) * 256 + cb), val);
                // prefetch xw for next step
                int tn = dir ? (T_SEQ - 2 - s) : (s + 1);
                const float* p = xw + ((size_t)(r0 + r) * T_SEQ + tn) * 1024 + cb;
                xi4 = __ldcs((const float4*)(p));
                xf4 = __ldcs((const float4*)(p + 256));
                xg4 = __ldcs((const float4*)(p + 512));
                xo4 = __ldcs((const float4*)(p + 768));
            }
        }
        if (s == T_SEQ - 1) break;
        __syncthreads();   // all h stores issued before tid0's release
        if (tid == 0)
            asm volatile("red.release.gpu.global.add.u32 [%0], %1;" :: "l"(ctr), "r"(1u) : "memory");
    }
}

// ---------------- head: layer-2 bwd single step + final dot + sigmoid ----------------
__global__ __launch_bounds__(256) void head_kernel(const float* __restrict__ Wi,
                                                   const float* __restrict__ b2,
                                                   const float* __restrict__ Wd,
                                                   const float* __restrict__ bd,
                                                   float* __restrict__ out) {
    __shared__ float xr[512];
    __shared__ float z[1024];
    __shared__ float red[8];
    const int b = blockIdx.x, tid = threadIdx.x;
    const float* xrow = g_x1 + ((size_t)b * T_SEQ + (T_SEQ - 1)) * 512;
    xr[tid] = xrow[tid];
    xr[tid + 256] = xrow[tid + 256];
    __syncthreads();
    const int c0 = tid * 4;
    float4 acc = *(const float4*)(b2 + c0);
    for (int k = 0; k < 512; k++) {
        float xv = xr[k];
        float4 wv = __ldg((const float4*)(Wi + (size_t)k * 1024 + c0));
        acc.x = fmaf(xv, wv.x, acc.x);
        acc.y = fmaf(xv, wv.y, acc.y);
        acc.z = fmaf(xv, wv.z, acc.z);
        acc.w = fmaf(xv, wv.w, acc.w);
    }
    *(float4*)(z + c0) = acc;
    __syncthreads();
    float zi = z[tid], zg = z[512 + tid], zo = z[768 + tid];
    float cst = sigf(zi) * tanhf(zg);           // c0 = 0 so forget term vanishes
    float h2b = sigf(zo) * tanhf(cst);
    float pl = g_h2f[b * 256 + tid] * __ldg(&Wd[tid]) + h2b * __ldg(&Wd[256 + tid]);
    #pragma unroll
    for (int off = 16; off; off >>= 1) pl += __shfl_down_sync(0xffffffffu, pl, off);
    if ((tid & 31) == 0) red[tid >> 5] = pl;
    __syncthreads();
    if (tid == 0) {
        float ssum = 0.f;
        #pragma unroll
        for (int q = 0; q < 8; q++) ssum += red[q];
        out[b] = sigf(ssum + bd[0]);
    }
}

// ---------------- launch ----------------
extern "C" void kernel_launch(void* const* d_in, const int* in_sizes, int n_in,
                              void* d_out, int out_size) {
    const int*   tokens = (const int*)  d_in[0];
    const float* embed  = (const float*)d_in[1];
    const float* fw1_Wi = (const float*)d_in[2];
    const float* fw1_Wh = (const float*)d_in[3];
    const float* fw1_b  = (const float*)d_in[4];
    const float* bw1_Wi = (const float*)d_in[5];
    const float* bw1_Wh = (const float*)d_in[6];
    const float* bw1_b  = (const float*)d_in[7];
    const float* fw2_Wi = (const float*)d_in[8];
    const float* fw2_Wh = (const float*)d_in[9];
    const float* fw2_b  = (const float*)d_in[10];
    const float* bw2_Wi = (const float*)d_in[11];
    const float* bw2_b  = (const float*)d_in[13];
    const float* Wd     = (const float*)d_in[14];
    const float* bd     = (const float*)d_in[15];
    float* out = (float*)d_out;

    float *px, *pxw1f, *pxw1b, *pxw2, *px1, *ph2f;
    __nv_bfloat16* phb;
    unsigned* pctrs;
    cudaGetSymbolAddress((void**)&px,    g_x);
    cudaGetSymbolAddress((void**)&pxw1f, g_xw1f);
    cudaGetSymbolAddress((void**)&pxw1b, g_xw1b);
    cudaGetSymbolAddress((void**)&pxw2,  g_xw2);
    cudaGetSymbolAddress((void**)&px1,   g_x1);
    cudaGetSymbolAddress((void**)&ph2f,  g_h2f);
    cudaGetSymbolAddress((void**)&phb,   g_hb);
    cudaGetSymbolAddress((void**)&pctrs, g_ctrs);

    cudaFuncSetAttribute(scan_kernel, cudaFuncAttributeMaxDynamicSharedMemorySize, SCAN_SMEM);

    init_kernel<<<1, 32>>>();
    gather_kernel<<<16384, 256>>>(tokens, embed);
    gemm_bf16<<<dim3(8, 512), 256>>>(px, fw1_Wi, pxw1f, 1024, 256);
    gemm_bf16<<<dim3(8, 512), 256>>>(px, bw1_Wi, pxw1b, 1024, 256);
    scan_kernel<<<64, 256, SCAN_SMEM>>>(pxw1f, pxw1b, fw1_Wh, bw1_Wh, fw1_b, bw1_b,
                                        phb, pctrs, px1, nullptr);
    gemm_bf16<<<dim3(8, 512), 256>>>(px1, fw2_Wi, pxw2, 1024, 512);
    scan_kernel<<<32, 256, SCAN_SMEM>>>(pxw2, pxw2, fw2_Wh, fw2_Wh, fw2_b, fw2_b,
                                        phb + (size_t)2 * 2 * (B_SZ * 256), pctrs + 16,
                                        nullptr, ph2f);
    head_kernel<<<64, 256>>>(bw2_Wi, bw2_b, Wd, bd, out);
}

// round 9
// speedup vs baseline: 1.4430x; 1.3405x over previous
#include <cuda_runtime.h>
#include <cuda_bf16.h>
#include <mma.h>
#include <cstdint>
#include <cstddef>

using namespace nvcuda;

#define T_SEQ 1024
#define B_SZ  64
// E = 256, H = 256, 4H = 1024

// ---------------- device-global scratch (no allocations) ----------------
__device__ float g_x   [(size_t)B_SZ * T_SEQ * 256];   // gathered embeddings
__device__ float g_xw1f[(size_t)B_SZ * T_SEQ * 1024];  // x @ fw1_Wi
__device__ float g_xw1b[(size_t)B_SZ * T_SEQ * 1024];  // x @ bw1_Wi
__device__ float g_xw2 [(size_t)B_SZ * T_SEQ * 1024];  // x1 @ fw2_Wi
__device__ float g_x1  [(size_t)B_SZ * T_SEQ * 512];   // layer-1 output [fwd|bwd]
__device__ float g_h2f [B_SZ * 256];                   // layer-2 fwd final h
__device__ __nv_bfloat16 g_hb[3][2][B_SZ * 256];       // h double buffers (l1f, l1b, l2)
__device__ unsigned g_ctrs[32];                        // group barrier counters

// ---------------- helpers ----------------
__device__ __forceinline__ float sigf(float x) {
    return __fdividef(1.0f, 1.0f + __expf(-x));
}
__device__ __forceinline__ float tanhfast(float x) {
    float e = __expf(2.0f * x);
    return 1.0f - __fdividef(2.0f, e + 1.0f);
}

// ---------------- init: zero barrier counters (every replay) ----------------
__global__ void init_kernel() {
    int i = threadIdx.x;
    if (i < 32) g_ctrs[i] = 0u;
}

// ---------------- embedding gather ----------------
__global__ void gather_kernel(const int* __restrict__ tok, const float* __restrict__ emb) {
    size_t idx = (size_t)blockIdx.x * blockDim.x + threadIdx.x;  // 65536*64 float4
    int row = (int)(idx >> 6);
    int f   = (int)(idx & 63);
    int t   = __ldg(&tok[row]);
    ((float4*)g_x)[idx] = __ldg(&((const float4*)emb)[(size_t)t * 64 + f]);
}

// ---------------- bf16 WMMA GEMM: C[M,N] = A[M,K] @ B[K,N] ----------------
#define GLDA 40
#define GLDB 136
__global__ __launch_bounds__(256) void gemm_bf16(const float* __restrict__ A,
                                                 const float* __restrict__ B,
                                                 float* __restrict__ C,
                                                 int N, int K) {
    __shared__ __nv_bfloat16 As[128 * GLDA];
    __shared__ __nv_bfloat16 Bs[32 * GLDB];
    const int tid = threadIdx.x;
    const int w   = tid >> 5;
    const int m0  = blockIdx.y * 128;
    const int n0  = blockIdx.x * 128;
    const int wm0 = (w >> 2) * 64;
    const int wn0 = (w & 3) * 32;

    wmma::fragment<wmma::accumulator, 16, 16, 16, float> c[4][2];
    #pragma unroll
    for (int i = 0; i < 4; i++)
        #pragma unroll
        for (int j = 0; j < 2; j++) wmma::fill_fragment(c[i][j], 0.0f);

    const int nkt = K >> 5;
    for (int kt = 0; kt < nkt; kt++) {
        #pragma unroll
        for (int p = 0; p < 4; p++) {
            int idx = tid + p * 256;
            int row = idx >> 3, c4 = idx & 7;
            float4 v = __ldg(&((const float4*)(A + (size_t)(m0 + row) * K + kt * 32))[c4]);
            __nv_bfloat162* dst = (__nv_bfloat162*)(As + row * GLDA + c4 * 4);
            dst[0] = __floats2bfloat162_rn(v.x, v.y);
            dst[1] = __floats2bfloat162_rn(v.z, v.w);
        }
        #pragma unroll
        for (int p = 0; p < 4; p++) {
            int idx = tid + p * 256;
            int row = idx >> 5, c4 = idx & 31;
            float4 v = __ldg(&((const float4*)(B + (size_t)(kt * 32 + row) * N + n0))[c4]);
            __nv_bfloat162* dst = (__nv_bfloat162*)(Bs + row * GLDB + c4 * 4);
            dst[0] = __floats2bfloat162_rn(v.x, v.y);
            dst[1] = __floats2bfloat162_rn(v.z, v.w);
        }
        __syncthreads();
        #pragma unroll
        for (int kk = 0; kk < 32; kk += 16) {
            wmma::fragment<wmma::matrix_a, 16, 16, 16, __nv_bfloat16, wmma::row_major> a[4];
            wmma::fragment<wmma::matrix_b, 16, 16, 16, __nv_bfloat16, wmma::row_major> b[2];
            #pragma unroll
            for (int i = 0; i < 4; i++)
                wmma::load_matrix_sync(a[i], &As[(wm0 + i * 16) * GLDA + kk], GLDA);
            #pragma unroll
            for (int j = 0; j < 2; j++)
                wmma::load_matrix_sync(b[j], &Bs[kk * GLDB + wn0 + j * 16], GLDB);
            #pragma unroll
            for (int i = 0; i < 4; i++)
                #pragma unroll
                for (int j = 0; j < 2; j++)
                    wmma::mma_sync(c[i][j], a[i], b[j], c[i][j]);
        }
        __syncthreads();
    }
    #pragma unroll
    for (int i = 0; i < 4; i++)
        #pragma unroll
        for (int j = 0; j < 2; j++)
            wmma::store_matrix_sync(C + (size_t)(m0 + wm0 + i * 16) * N + n0 + wn0 + j * 16,
                                    c[i][j], N, wmma::mem_row_major);
}

// ---------------- persistent LSTM scan (R4 topology + K-split MMA) ----------------
// Grid: nDir*128 CTAs, 256 threads. CTA (dir, bg, ng): batch rows bg*8..+8,
// h-cols ng*16..+16 (=> 64 local z-cols, c = gate*16 + j). Wh slice in SMEM.
// h exchanged via global bf16 double buffer + per-group (16 CTA) counter.
// MMA K-split: warp w -> K-half q=w>>2 (128 k each), cols n0=(w&3)*16; 8-deep chain.
#define WHS_LD 72
#define HS_LD  264
#define ZB_LD  68
#define WHS_BYTES (256 * WHS_LD * 2)          // 36864
#define HS_OFF    WHS_BYTES
#define HS_BYTES  (16 * HS_LD * 2)            // 8448
#define ZB_OFF    (HS_OFF + HS_BYTES)         // 45312
#define ZB_BYTES  (2 * 16 * ZB_LD * 4)        // 8704 (two K-half planes)
#define SCAN_SMEM (ZB_OFF + ZB_BYTES)         // 54016

__global__ __launch_bounds__(256, 2) void scan_kernel(
    const float* __restrict__ xw_f, const float* __restrict__ xw_b,
    const float* __restrict__ Wh_f, const float* __restrict__ Wh_b,
    const float* __restrict__ b_f,  const float* __restrict__ b_b,
    __nv_bfloat16* hb_base, unsigned* ctrs,
    float* x1out, float* h2out) {
    extern __shared__ char sm[];
    __nv_bfloat16* Whs = (__nv_bfloat16*)sm;
    __nv_bfloat16* hs  = (__nv_bfloat16*)(sm + HS_OFF);
    float*         zb  = (float*)(sm + ZB_OFF);

    const int tid = threadIdx.x;
    const int w   = tid >> 5;
    const int dir = blockIdx.x >> 7;              // scan2 grid=128 -> always 0
    const int sub = blockIdx.x & 127;
    const int bg  = sub >> 4, ng = sub & 15;
    const int r0  = bg * 8, hc0 = ng * 16;

    const float* xw   = dir ? xw_b : xw_f;
    const float* Whg  = dir ? Wh_b : Wh_f;
    const float* bias = dir ? b_b  : b_f;
    __nv_bfloat16* hb = hb_base + (size_t)dir * 2 * (B_SZ * 256);
    unsigned* ctr = ctrs + dir * 8 + bg;

    // zero hs once (rows 8..15 stay zero forever -> M padded to 16)
    for (int i = tid; i < 16 * HS_LD; i += 256) hs[i] = __float2bfloat16(0.f);
    // stage Wh slice bf16: Whs[k][c], c = gate*16+j -> global col gate*256+hc0+j
    for (int i = tid; i < 256 * 64; i += 256) {
        int k = i >> 6, cc = i & 63;
        int gt = cc >> 4, j = cc & 15;
        Whs[k * WHS_LD + cc] =
            __float2bfloat16_rn(__ldg(&Whg[(size_t)k * 1024 + gt * 256 + hc0 + j]));
    }

    // h-load role: row lrow (0..7), 8 bf16 (16B) per thread
    const int lrow = tid >> 5;
    const int lcol = (tid & 31) * 8;
    // MMA role: K-half q, local col base n0
    const int q  = w >> 2;
    const int n0 = (w & 3) * 16;
    // gate role (tid < 128): row gr, h-col gj
    const int gr = tid >> 4, gj = tid & 15;
    const int xwbase = hc0 + gj;
    float bi = 0.f, bfv = 0.f, bgv = 0.f, bo = 0.f;
    if (tid < 128) {
        bi  = __ldg(&bias[0 * 256 + xwbase]);
        bfv = __ldg(&bias[1 * 256 + xwbase]);
        bgv = __ldg(&bias[2 * 256 + xwbase]);
        bo  = __ldg(&bias[3 * 256 + xwbase]);
    }
    float c_state = 0.0f;
    __syncthreads();

    // prefetch xw for step 0
    float xwi = 0.f, xwf = 0.f, xwg = 0.f, xwo = 0.f;
    if (tid < 128) {
        int t0 = dir ? (T_SEQ - 1) : 0;
        const float* p = xw + ((size_t)(r0 + gr) * T_SEQ + t0) * 1024 + xwbase;
        xwi = __ldcs(p); xwf = __ldcs(p + 256); xwg = __ldcs(p + 512); xwo = __ldcs(p + 768);
    }

    for (int s = 0; s < T_SEQ; s++) {
        const int t_in = dir ? (T_SEQ - 1 - s) : s;

        if (s > 0) {
            // wait for all 16 group CTAs to have published h(s)
            if (tid == 0) {
                const unsigned tgt = 16u * (unsigned)s;
                unsigned v;
                do {
                    asm volatile("ld.acquire.gpu.global.u32 %0, [%1];" : "=r"(v) : "l"(ctr) : "memory");
                } while (v < tgt);
            }
            __syncthreads();
            // load h(s) [8 rows x 256] bf16 from L2 into hs rows 0..7
            {
                const __nv_bfloat16* hread = hb + (s & 1) * (B_SZ * 256) + (r0 + lrow) * 256 + lcol;
                uint4 hv = __ldcg((const uint4*)hread);
                *(uint4*)(hs + lrow * HS_LD + lcol) = hv;
            }
            __syncthreads();
            // K-split MMA: warp (q, n0); 8-deep chain over its 128 k
            {
                wmma::fragment<wmma::accumulator, 16, 16, 16, float> acc;
                wmma::fill_fragment(acc, 0.0f);
                const int kbase = q * 128;
                #pragma unroll
                for (int kt = 0; kt < 8; kt++) {
                    wmma::fragment<wmma::matrix_a, 16, 16, 16, __nv_bfloat16, wmma::row_major> a;
                    wmma::fragment<wmma::matrix_b, 16, 16, 16, __nv_bfloat16, wmma::row_major> b;
                    const int kk = kbase + kt * 16;
                    wmma::load_matrix_sync(a, hs + kk, HS_LD);
                    wmma::load_matrix_sync(b, Whs + kk * WHS_LD + n0, WHS_LD);
                    wmma::mma_sync(acc, a, b, acc);
                }
                wmma::store_matrix_sync(zb + q * (16 * ZB_LD) + n0, acc, ZB_LD, wmma::mem_row_major);
            }
        }
        __syncthreads();

        // gates: thread (gr, gj) -> row r0+gr, h-col hc0+gj
        if (tid < 128) {
            float zi = bi + xwi, zf = bfv + xwf, zg = bgv + xwg, zo = bo + xwo;
            if (s > 0) {
                const float* z0 = zb + gr * ZB_LD;
                const float* z1 = z0 + 16 * ZB_LD;
                zi += z0[gj]      + z1[gj];
                zf += z0[16 + gj] + z1[16 + gj];
                zg += z0[32 + gj] + z1[32 + gj];
                zo += z0[48 + gj] + z1[48 + gj];
            }
            c_state = sigf(zf) * c_state + sigf(zi) * tanhfast(zg);
            float hval = sigf(zo) * tanhfast(c_state);

            if (x1out)
                __stcg(x1out + ((size_t)(r0 + gr) * T_SEQ + t_in) * 512 + dir * 256 + hc0 + gj, hval);
            if (h2out && s == T_SEQ - 1)
                h2out[(r0 + gr) * 256 + hc0 + gj] = hval;

            if (s < T_SEQ - 1) {
                // publish h(s+1) bf16 to global double buffer
                __nv_bfloat16 hv = __float2bfloat16_rn(hval);
                __stcg((__nv_bfloat16*)(hb + ((s + 1) & 1) * (B_SZ * 256) + (r0 + gr) * 256 + hc0 + gj), hv);
                // prefetch xw for next step (DRAM latency hides under barrier)
                int tn = dir ? (T_SEQ - 2 - s) : (s + 1);
                const float* p = xw + ((size_t)(r0 + gr) * T_SEQ + tn) * 1024 + xwbase;
                xwi = __ldcs(p); xwf = __ldcs(p + 256); xwg = __ldcs(p + 512); xwo = __ldcs(p + 768);
            }
        }
        if (s == T_SEQ - 1) break;

        __syncthreads();   // all h stores issued before tid0's release
        if (tid == 0)
            asm volatile("red.release.gpu.global.add.u32 [%0], %1;" :: "l"(ctr), "r"(1u) : "memory");
    }
}

// ---------------- head: layer-2 bwd single step + final dot + sigmoid ----------------
__global__ __launch_bounds__(256) void head_kernel(const float* __restrict__ Wi,
                                                   const float* __restrict__ b2,
                                                   const float* __restrict__ Wd,
                                                   const float* __restrict__ bd,
                                                   float* __restrict__ out) {
    __shared__ float xr[512];
    __shared__ float z[1024];
    __shared__ float red[8];
    const int b = blockIdx.x, tid = threadIdx.x;
    const float* xrow = g_x1 + ((size_t)b * T_SEQ + (T_SEQ - 1)) * 512;
    xr[tid] = xrow[tid];
    xr[tid + 256] = xrow[tid + 256];
    __syncthreads();
    const int c0 = tid * 4;
    float4 acc = *(const float4*)(b2 + c0);
    for (int k = 0; k < 512; k++) {
        float xv = xr[k];
        float4 wv = __ldg((const float4*)(Wi + (size_t)k * 1024 + c0));
        acc.x = fmaf(xv, wv.x, acc.x);
        acc.y = fmaf(xv, wv.y, acc.y);
        acc.z = fmaf(xv, wv.z, acc.z);
        acc.w = fmaf(xv, wv.w, acc.w);
    }
    *(float4*)(z + c0) = acc;
    __syncthreads();
    float zi = z[tid], zg = z[512 + tid], zo = z[768 + tid];
    float cst = sigf(zi) * tanhf(zg);           // c0 = 0 so forget term vanishes
    float h2b = sigf(zo) * tanhf(cst);
    float pl = g_h2f[b * 256 + tid] * __ldg(&Wd[tid]) + h2b * __ldg(&Wd[256 + tid]);
    #pragma unroll
    for (int off = 16; off; off >>= 1) pl += __shfl_down_sync(0xffffffffu, pl, off);
    if ((tid & 31) == 0) red[tid >> 5] = pl;
    __syncthreads();
    if (tid == 0) {
        float ssum = 0.f;
        #pragma unroll
        for (int q = 0; q < 8; q++) ssum += red[q];
        out[b] = sigf(ssum + bd[0]);
    }
}

// ---------------- launch ----------------
extern "C" void kernel_launch(void* const* d_in, const int* in_sizes, int n_in,
                              void* d_out, int out_size) {
    const int*   tokens = (const int*)  d_in[0];
    const float* embed  = (const float*)d_in[1];
    const float* fw1_Wi = (const float*)d_in[2];
    const float* fw1_Wh = (const float*)d_in[3];
    const float* fw1_b  = (const float*)d_in[4];
    const float* bw1_Wi = (const float*)d_in[5];
    const float* bw1_Wh = (const float*)d_in[6];
    const float* bw1_b  = (const float*)d_in[7];
    const float* fw2_Wi = (const float*)d_in[8];
    const float* fw2_Wh = (const float*)d_in[9];
    const float* fw2_b  = (const float*)d_in[10];
    const float* bw2_Wi = (const float*)d_in[11];
    const float* bw2_b  = (const float*)d_in[13];
    const float* Wd     = (const float*)d_in[14];
    const float* bd     = (const float*)d_in[15];
    float* out = (float*)d_out;

    float *px, *pxw1f, *pxw1b, *pxw2, *px1, *ph2f;
    __nv_bfloat16* phb;
    unsigned* pctrs;
    cudaGetSymbolAddress((void**)&px,    g_x);
    cudaGetSymbolAddress((void**)&pxw1f, g_xw1f);
    cudaGetSymbolAddress((void**)&pxw1b, g_xw1b);
    cudaGetSymbolAddress((void**)&pxw2,  g_xw2);
    cudaGetSymbolAddress((void**)&px1,   g_x1);
    cudaGetSymbolAddress((void**)&ph2f,  g_h2f);
    cudaGetSymbolAddress((void**)&phb,   g_hb);
    cudaGetSymbolAddress((void**)&pctrs, g_ctrs);

    cudaFuncSetAttribute(scan_kernel, cudaFuncAttributeMaxDynamicSharedMemorySize, SCAN_SMEM);

    init_kernel<<<1, 32>>>();
    gather_kernel<<<16384, 256>>>(tokens, embed);
    gemm_bf16<<<dim3(8, 512), 256>>>(px, fw1_Wi, pxw1f, 1024, 256);
    gemm_bf16<<<dim3(8, 512), 256>>>(px, bw1_Wi, pxw1b, 1024, 256);
    scan_kernel<<<256, 256, SCAN_SMEM>>>(pxw1f, pxw1b, fw1_Wh, bw1_Wh, fw1_b, bw1_b,
                                         phb, pctrs, px1, nullptr);
    gemm_bf16<<<dim3(8, 512), 256>>>(px1, fw2_Wi, pxw2, 1024, 512);
    scan_kernel<<<128, 256, SCAN_SMEM>>>(pxw2, pxw2, fw2_Wh, fw2_Wh, fw2_b, fw2_b,
                                         phb + (size_t)2 * 2 * (B_SZ * 256), pctrs + 16,
                                         nullptr, ph2f);
    head_kernel<<<64, 256>>>(bw2_Wi, bw2_b, Wd, bd, out);
}